// round 4
// baseline (speedup 1.0000x reference)
#include <cuda_runtime.h>
#include <math.h>

// Triplet-margin ranking loss, GB300 sm_103a — single fused streaming kernel,
// d_ap computed once by block 0 and published via release/acquire flag.
// anchor: (1, 2400) f32, positive: (P=5, 2400) f32, negative: (N=100000, 2400) f32
// loss = sum_{i<num_full} relu(d_ap[i % P] - d_an[i] + MARGIN)
// d_x = || anchor - x + EPS ||_2  (elementwise +EPS, torch pairwise_distance)

#define EPS    1e-6f
#define MARGIN 1.0f
#define DIM    2400
#define DIM4   (DIM / 4)   // 600 float4 per row

__device__ float        g_dap[8];   // d_ap values (P <= 8; problem has P=5)
__device__ volatile int g_flag;     // release flag; reset by memset each launch

// ---------------------------------------------------------------------------
__global__ void __launch_bounds__(256, 8)
loss_kernel(const float* __restrict__ anchor,
            const float* __restrict__ pos,
            const float* __restrict__ neg,
            float* __restrict__ out,
            int num_full, int P)
{
    __shared__ float4 sA[DIM4];        // anchor, 9600 B
    __shared__ float  sWarp[8];

    const int wid  = threadIdx.x >> 5;
    const int lane = threadIdx.x & 31;

    // ---- stage anchor into shared (all blocks) ----
    const float4* a4 = reinterpret_cast<const float4*>(anchor);
    for (int k = threadIdx.x; k < DIM4; k += blockDim.x)
        sA[k] = a4[k];

    // ---- block 0 only: compute d_ap (48 KB read ONCE chip-wide) ----
    if (blockIdx.x == 0 && wid < P) {
        const float4* p4 = reinterpret_cast<const float4*>(pos + (size_t)wid * DIM);
        float s = 0.0f;
        #pragma unroll 4
        for (int k = lane; k < DIM4; k += 32) {
            float4 a = a4[k];            // anchor from global (smem not synced yet)
            float4 p = __ldg(&p4[k]);
            float d0 = a.x - p.x + EPS;
            float d1 = a.y - p.y + EPS;
            float d2 = a.z - p.z + EPS;
            float d3 = a.w - p.w + EPS;
            s = fmaf(d0, d0, s);
            s = fmaf(d1, d1, s);
            s = fmaf(d2, d2, s);
            s = fmaf(d3, d3, s);
        }
        #pragma unroll
        for (int o = 16; o > 0; o >>= 1)
            s += __shfl_xor_sync(0xFFFFFFFFu, s, o);
        if (lane == 0) g_dap[wid] = sqrtf(s);
    }
    __syncthreads();                     // anchor staged; block0: d_ap written

    if (blockIdx.x == 0 && threadIdx.x == 0) {
        __threadfence();                 // publish g_dap
        g_flag = 1;                      // release
    }

    // ---- static warp-per-row grid-stride over negatives ----
    const int nwarps = blockDim.x >> 5;
    const int gwarp  = blockIdx.x * nwarps + wid;
    const int W      = gridDim.x * nwarps;

    float dapv     = 0.0f;               // lane j (j<P) will hold d_ap[j]
    bool  have_dap = false;
    float acc      = 0.0f;

    for (int row = gwarp; row < num_full; row += W) {
        const float4* n4 = reinterpret_cast<const float4*>(neg + (size_t)row * DIM);
        float s = 0.0f;
        // 600 float4 / 32 lanes = 18.75 iterations; unroll for MLP
        #pragma unroll 4
        for (int k = lane; k < DIM4; k += 32) {
            float4 a = sA[k];
            float4 n = __ldg(&n4[k]);
            float d0 = a.x - n.x + EPS;
            float d1 = a.y - n.y + EPS;
            float d2 = a.z - n.z + EPS;
            float d3 = a.w - n.w + EPS;
            s = fmaf(d0, d0, s);
            s = fmaf(d1, d1, s);
            s = fmaf(d2, d2, s);
            s = fmaf(d3, d3, s);
        }
        #pragma unroll
        for (int o = 16; o > 0; o >>= 1)
            s += __shfl_xor_sync(0xFFFFFFFFu, s, o);   // butterfly: all lanes hold s

        if (!have_dap) {
            // First combine for this warp (~2us in; flag is up by ~1.5us).
            // Plain volatile poll — NOT an atomic (single-address atomics
            // serialized catastrophically in R2).
            while (g_flag == 0) { }
            __threadfence();             // acquire
            if (lane < P) dapv = *((volatile float*)&g_dap[lane]);
            have_dap = true;
        }

        float dapj = __shfl_sync(0xFFFFFFFFu, dapv, row % P);
        if (lane == 0) {
            float t = dapj - sqrtf(s) + MARGIN;
            acc += (t > 0.0f) ? t : 0.0f;
        }
    }

    // ---- block reduction + single atomic ----
    if (lane == 0) sWarp[wid] = acc;
    __syncthreads();
    if (threadIdx.x == 0) {
        float bsum = 0.0f;
        #pragma unroll
        for (int i = 0; i < 8; i++) bsum += sWarp[i];
        atomicAdd(out, bsum);
    }
}

// ---------------------------------------------------------------------------
extern "C" void kernel_launch(void* const* d_in, const int* in_sizes, int n_in,
                              void* d_out, int out_size)
{
    const float* anchor = (const float*)d_in[0];
    const float* pos    = (const float*)d_in[1];
    const float* neg    = (const float*)d_in[2];
    float* out = (float*)d_out;

    const int P = in_sizes[1] / DIM;          // 5
    const int N = in_sizes[2] / DIM;          // 100000
    const int num_full = (N / P) * P;         // 100000

    // zero the poisoned output scalar + the release flag (graph-capturable)
    cudaMemsetAsync(d_out, 0, sizeof(float));
    void* flag_addr = nullptr;
    cudaGetSymbolAddress(&flag_addr, g_flag);
    cudaMemsetAsync(flag_addr, 0, sizeof(int));

    // exactly one resident wave: 8 blocks of 256 threads per SM
    int sm_count = 148;
    cudaDeviceGetAttribute(&sm_count, cudaDevAttrMultiProcessorCount, 0);
    const int grid = sm_count * 8;
    loss_kernel<<<grid, 256>>>(anchor, pos, neg, out, num_full, P);
}